// round 8
// baseline (speedup 1.0000x reference)
#include <cuda_runtime.h>

// FokkerPlanck2D step, two-kernel scheme:
//  K1 (tiny, 3-way split): fold A (drift) + D (diffusion) + dt into 9
//      per-point stencil weight planes W[9][512][512] (batch-independent,
//      boundary logic baked in). grid (512, 3) for short per-thread chains.
//  K2 (hot): out(b,i,j) = max(0, sum_9 W_o(i,j) * f(b, i+di, j+dj)).
//      i-pencil blocks, 128 threads x float4 = full row, NBATCH=4 batches
//      share the 9 weight vectors; f rows rotate through 6-wide register
//      windows (NOT unrolled: reg cap makes unrolling counterproductive, R7).
//      f halos come from warp shuffles; only warp-boundary lanes do a
//      predicated 1-lane scalar load (kills ~32 L1 wavefronts/warp-iter).
// Weight planes: 0:Wc 1:Wxp 2:Wxm 3:Wyp 4:Wym 5:Wpp 6:Wpm 7:Wmp 8:Wmm

static constexpr int NXC    = 512;
static constexpr int NYC    = 512;
static constexpr int ICH    = 16;
static constexpr int NBATCH = 4;
static constexpr int TPB    = NYC / 4;      // 128
static constexpr long PLANE = (long)NXC * NYC;

__device__ float g_w[9 * NXC * NYC];        // 9.4 MB scratch (L2-resident)

// Full-warp-scalar halo version (used in K1 where rows are read once).
__device__ __forceinline__ void win6_g(const float* __restrict__ row, int j0,
                                       bool Lg, bool Rg, float v[6]) {
    const float4 m4 = __ldg(reinterpret_cast<const float4*>(row + j0));
    v[0] = Lg ? __ldg(row + j0 - 1) : 0.0f;
    v[1] = m4.x; v[2] = m4.y; v[3] = m4.z; v[4] = m4.w;
    v[5] = Rg ? __ldg(row + j0 + 4) : 0.0f;
}

// Shuffle-halo version (used in K2 hot loop). Halos from neighbor lanes;
// warp-boundary lanes use a predicated single-lane scalar load.
__device__ __forceinline__ void win6_shfl(const float* __restrict__ row, int j0,
                                          int lane, bool Lg, bool Rg, float v[6]) {
    const float4 m4 = __ldg(reinterpret_cast<const float4*>(row + j0));
    float left  = __shfl_up_sync(0xffffffffu, m4.w, 1);
    float right = __shfl_down_sync(0xffffffffu, m4.x, 1);
    if (lane == 0)  left  = Lg ? __ldg(row + j0 - 1) : 0.0f;
    if (lane == 31) right = Rg ? __ldg(row + j0 + 4) : 0.0f;
    v[0] = left;
    v[1] = m4.x; v[2] = m4.y; v[3] = m4.z; v[4] = m4.w;
    v[5] = right;
}

__global__ __launch_bounds__(TPB)
void fp2d_weights_kernel(const float* __restrict__ A,
                         const float* __restrict__ D,
                         const float* __restrict__ dtp) {
    const int tid = threadIdx.x;
    const int j0  = tid * 4;
    const bool L  = (tid > 0);
    const bool R  = (tid < TPB - 1);
    const int i   = blockIdx.x;
    const int grp = blockIdx.y;

    const float dt  = __ldg(dtp);
    const float hdt = 0.5f  * dt;
    const float qdt = 0.25f * dt;

    const float* A0 = A;
    const float* A1 = A + PLANE;
    const float* D0 = D;
    const float* D1 = D + PLANE;
    const float* D2 = D + 2 * PLANE;

    float w0[4], w1[4], w2[4];
    int p0, p1, p2;

    if (grp == 0) {
        // center-row weights: Wc(0), Wyp(3), Wym(4)
        p0 = 0; p1 = 3; p2 = 4;
        const float4 d0 = __ldg(reinterpret_cast<const float4*>(D0 + (long)i * NYC + j0));
        float d1w[6], a1w[6];
        win6_g(D1 + (long)i * NYC, j0, L, R, d1w);
        win6_g(A1 + (long)i * NYC, j0, L, R, a1w);
        const float d0v[4] = {d0.x, d0.y, d0.z, d0.w};
        #pragma unroll
        for (int k = 0; k < 4; ++k) {
            w0[k] = 1.0f - dt * (d0v[k] + d1w[k + 1]);
            w1[k] = hdt * (d1w[k + 2] - a1w[k + 2]);
            w2[k] = hdt * (d1w[k]     + a1w[k]);
        }
    } else if (grp == 1) {
        // i+1-row weights: Wxp(1), Wpp(5), Wpm(6)
        p0 = 1; p1 = 5; p2 = 6;
        const int ip = i + 1;
        if (ip < NXC) {
            const float4 a0 = __ldg(reinterpret_cast<const float4*>(A0 + (long)ip * NYC + j0));
            const float4 d0 = __ldg(reinterpret_cast<const float4*>(D0 + (long)ip * NYC + j0));
            const float a0v[4] = {a0.x, a0.y, a0.z, a0.w};
            const float d0v[4] = {d0.x, d0.y, d0.z, d0.w};
            float d2w[6];
            win6_g(D2 + (long)ip * NYC, j0, L, R, d2w);
            #pragma unroll
            for (int k = 0; k < 4; ++k) {
                w0[k] =  hdt * (d0v[k] - a0v[k]);
                w1[k] =  qdt * d2w[k + 2];
                w2[k] = -qdt * d2w[k];
            }
        } else {
            #pragma unroll
            for (int k = 0; k < 4; ++k) { w0[k] = 0.f; w1[k] = 0.f; w2[k] = 0.f; }
        }
    } else {
        // i-1-row weights: Wxm(2), Wmp(7), Wmm(8)
        p0 = 2; p1 = 7; p2 = 8;
        const int im = i - 1;
        if (im >= 0) {
            const float4 a0 = __ldg(reinterpret_cast<const float4*>(A0 + (long)im * NYC + j0));
            const float4 d0 = __ldg(reinterpret_cast<const float4*>(D0 + (long)im * NYC + j0));
            const float a0v[4] = {a0.x, a0.y, a0.z, a0.w};
            const float d0v[4] = {d0.x, d0.y, d0.z, d0.w};
            float d2w[6];
            win6_g(D2 + (long)im * NYC, j0, L, R, d2w);
            #pragma unroll
            for (int k = 0; k < 4; ++k) {
                w0[k] =  hdt * (d0v[k] + a0v[k]);
                w1[k] = -qdt * d2w[k + 2];
                w2[k] =  qdt * d2w[k];
            }
        } else {
            #pragma unroll
            for (int k = 0; k < 4; ++k) { w0[k] = 0.f; w1[k] = 0.f; w2[k] = 0.f; }
        }
    }

    const long off = (long)i * NYC + j0;
    float4 v;
    v.x = w0[0]; v.y = w0[1]; v.z = w0[2]; v.w = w0[3];
    *reinterpret_cast<float4*>(g_w + p0 * PLANE + off) = v;
    v.x = w1[0]; v.y = w1[1]; v.z = w1[2]; v.w = w1[3];
    *reinterpret_cast<float4*>(g_w + p1 * PLANE + off) = v;
    v.x = w2[0]; v.y = w2[1]; v.z = w2[2]; v.w = w2[3];
    *reinterpret_cast<float4*>(g_w + p2 * PLANE + off) = v;
}

__global__ __launch_bounds__(TPB, 4)
void fp2d_step_kernel(const float* __restrict__ f,
                      float* __restrict__ out) {
    const int tid  = threadIdx.x;
    const int lane = tid & 31;
    const int j0   = tid * 4;
    const bool L   = (tid > 0);
    const bool R   = (tid < TPB - 1);
    const int i0   = blockIdx.x * ICH;
    const long b0  = (long)blockIdx.y * NBATCH;

    // f windows: [m] = f[row][j0+m-1], rotated along i
    float fm[NBATCH][6], fc[NBATCH][6], fp[NBATCH][6];

    // ---------------- prologue: f rows i0-1 and i0 ----------------
    {
        const int r = i0 - 1;
        if (r >= 0) {
            const float* frow = f + (long)r * NYC;
            #pragma unroll
            for (int b = 0; b < NBATCH; ++b)
                win6_shfl(frow + (b0 + b) * PLANE, j0, lane, L, R, fm[b]);
        } else {
            #pragma unroll
            for (int b = 0; b < NBATCH; ++b)
                #pragma unroll
                for (int m = 0; m < 6; ++m) fm[b][m] = 0.0f;
        }
        const float* frow = f + (long)i0 * NYC;
        #pragma unroll
        for (int b = 0; b < NBATCH; ++b)
            win6_shfl(frow + (b0 + b) * PLANE, j0, lane, L, R, fc[b]);
    }

    // ---------------- main i-march ----------------
    for (int i = i0; i < i0 + ICH; ++i) {
        const int ip = i + 1;

        // 1) load f row i+1 (the only DRAM-new data this iteration)
        if (ip < NXC) {
            const float* frow = f + (long)ip * NYC;
            #pragma unroll
            for (int b = 0; b < NBATCH; ++b)
                win6_shfl(frow + (b0 + b) * PLANE, j0, lane, L, R, fp[b]);
        } else {
            #pragma unroll
            for (int b = 0; b < NBATCH; ++b)
                #pragma unroll
                for (int m = 0; m < 6; ++m) fp[b][m] = 0.0f;
        }

        // 2) load the 9 precomputed weight vectors for row i (L2-hot)
        float4 w[9];
        const float* wrow = g_w + (long)i * NYC + j0;
        #pragma unroll
        for (int p = 0; p < 9; ++p)
            w[p] = __ldg(reinterpret_cast<const float4*>(wrow + p * PLANE));

        // 3) compute + streaming-store outputs for row i
        #pragma unroll
        for (int b = 0; b < NBATCH; ++b) {
            float rv[4];
            #pragma unroll
            for (int k = 0; k < 4; ++k) {
                const float wc  = (&w[0].x)[k];
                const float wxp = (&w[1].x)[k];
                const float wxm = (&w[2].x)[k];
                const float wyp = (&w[3].x)[k];
                const float wym = (&w[4].x)[k];
                const float wpp = (&w[5].x)[k];
                const float wpm = (&w[6].x)[k];
                const float wmp = (&w[7].x)[k];
                const float wmm = (&w[8].x)[k];
                float v = wc  * fc[b][k + 1];
                v += wxp * fp[b][k + 1];
                v += wxm * fm[b][k + 1];
                v += wyp * fc[b][k + 2];
                v += wym * fc[b][k];
                v += wpp * fp[b][k + 2];
                v += wpm * fp[b][k];
                v += wmp * fm[b][k + 2];
                v += wmm * fm[b][k];
                rv[k] = fmaxf(v, 0.0f);
            }
            float4 res;
            res.x = rv[0]; res.y = rv[1]; res.z = rv[2]; res.w = rv[3];
            __stcs(reinterpret_cast<float4*>(out + (b0 + b) * PLANE + (long)i * NYC + j0), res);
        }

        // 4) rotate f windows (fp -> fc -> fm)
        #pragma unroll
        for (int b = 0; b < NBATCH; ++b)
            #pragma unroll
            for (int m = 0; m < 6; ++m) {
                fm[b][m] = fc[b][m];
                fc[b][m] = fp[b][m];
            }
    }
}

extern "C" void kernel_launch(void* const* d_in, const int* in_sizes, int n_in,
                              void* d_out, int out_size) {
    const float* f  = (const float*)d_in[0];
    const float* A  = (const float*)d_in[1];
    const float* D  = (const float*)d_in[2];
    const float* dt = (const float*)d_in[3];
    float* out = (float*)d_out;

    const int plane = NXC * NYC;
    const int B = in_sizes[0] / plane;   // 128

    dim3 wgrid(NXC, 3);
    fp2d_weights_kernel<<<wgrid, TPB>>>(A, D, dt);
    dim3 grid(NXC / ICH, B / NBATCH);    // (32, 32)
    fp2d_step_kernel<<<grid, TPB>>>(f, out);
}

// round 9
// speedup vs baseline: 1.0693x; 1.0693x over previous
#include <cuda_runtime.h>

// FokkerPlanck2D step, two-kernel scheme (composition of proven-best pieces):
//  K1 (tiny, 3-way split, R7): fold A + D + dt into 9 per-point stencil
//      weight planes W[9][512][512] (batch-independent, boundary logic baked
//      in). grid (512, 3) for short per-thread load chains.
//  K2 (hot, R6 form): out(b,i,j) = max(0, sum_9 W_o(i,j) * f(b, i+di, j+dj)).
//      i-pencil blocks, 128 threads x float4 = full row, NBATCH=4 batches
//      share the 9 weight vectors; f rows rotate through 6-wide register
//      windows. Scalar halo loads (NOT shuffles: WARPSYNC serialization
//      regressed twice, R5/R8). NOT unrolled (reg cap, R7).
// Weight planes: 0:Wc 1:Wxp 2:Wxm 3:Wyp 4:Wym 5:Wpp 6:Wpm 7:Wmp 8:Wmm

static constexpr int NXC    = 512;
static constexpr int NYC    = 512;
static constexpr int ICH    = 16;
static constexpr int NBATCH = 4;
static constexpr int TPB    = NYC / 4;      // 128
static constexpr long PLANE = (long)NXC * NYC;

__device__ float g_w[9 * NXC * NYC];        // 9.4 MB scratch (L2-resident)

__device__ __forceinline__ void win6_g(const float* __restrict__ row, int j0,
                                       bool Lg, bool Rg, float v[6]) {
    // v[m] = row[j0 + m - 1], zero-filled outside [0, NYC)
    const float4 m4 = __ldg(reinterpret_cast<const float4*>(row + j0));
    v[0] = Lg ? __ldg(row + j0 - 1) : 0.0f;
    v[1] = m4.x; v[2] = m4.y; v[3] = m4.z; v[4] = m4.w;
    v[5] = Rg ? __ldg(row + j0 + 4) : 0.0f;
}

__global__ __launch_bounds__(TPB)
void fp2d_weights_kernel(const float* __restrict__ A,
                         const float* __restrict__ D,
                         const float* __restrict__ dtp) {
    const int tid = threadIdx.x;
    const int j0  = tid * 4;
    const bool L  = (tid > 0);
    const bool R  = (tid < TPB - 1);
    const int i   = blockIdx.x;
    const int grp = blockIdx.y;

    const float dt  = __ldg(dtp);
    const float hdt = 0.5f  * dt;
    const float qdt = 0.25f * dt;

    const float* A0 = A;
    const float* A1 = A + PLANE;
    const float* D0 = D;
    const float* D1 = D + PLANE;
    const float* D2 = D + 2 * PLANE;

    float w0[4], w1[4], w2[4];
    int p0, p1, p2;

    if (grp == 0) {
        // center-row weights: Wc(0), Wyp(3), Wym(4)
        p0 = 0; p1 = 3; p2 = 4;
        const float4 d0 = __ldg(reinterpret_cast<const float4*>(D0 + (long)i * NYC + j0));
        float d1w[6], a1w[6];
        win6_g(D1 + (long)i * NYC, j0, L, R, d1w);
        win6_g(A1 + (long)i * NYC, j0, L, R, a1w);
        const float d0v[4] = {d0.x, d0.y, d0.z, d0.w};
        #pragma unroll
        for (int k = 0; k < 4; ++k) {
            w0[k] = 1.0f - dt * (d0v[k] + d1w[k + 1]);
            w1[k] = hdt * (d1w[k + 2] - a1w[k + 2]);
            w2[k] = hdt * (d1w[k]     + a1w[k]);
        }
    } else if (grp == 1) {
        // i+1-row weights: Wxp(1), Wpp(5), Wpm(6)
        p0 = 1; p1 = 5; p2 = 6;
        const int ip = i + 1;
        if (ip < NXC) {
            const float4 a0 = __ldg(reinterpret_cast<const float4*>(A0 + (long)ip * NYC + j0));
            const float4 d0 = __ldg(reinterpret_cast<const float4*>(D0 + (long)ip * NYC + j0));
            const float a0v[4] = {a0.x, a0.y, a0.z, a0.w};
            const float d0v[4] = {d0.x, d0.y, d0.z, d0.w};
            float d2w[6];
            win6_g(D2 + (long)ip * NYC, j0, L, R, d2w);
            #pragma unroll
            for (int k = 0; k < 4; ++k) {
                w0[k] =  hdt * (d0v[k] - a0v[k]);
                w1[k] =  qdt * d2w[k + 2];
                w2[k] = -qdt * d2w[k];
            }
        } else {
            #pragma unroll
            for (int k = 0; k < 4; ++k) { w0[k] = 0.f; w1[k] = 0.f; w2[k] = 0.f; }
        }
    } else {
        // i-1-row weights: Wxm(2), Wmp(7), Wmm(8)
        p0 = 2; p1 = 7; p2 = 8;
        const int im = i - 1;
        if (im >= 0) {
            const float4 a0 = __ldg(reinterpret_cast<const float4*>(A0 + (long)im * NYC + j0));
            const float4 d0 = __ldg(reinterpret_cast<const float4*>(D0 + (long)im * NYC + j0));
            const float a0v[4] = {a0.x, a0.y, a0.z, a0.w};
            const float d0v[4] = {d0.x, d0.y, d0.z, d0.w};
            float d2w[6];
            win6_g(D2 + (long)im * NYC, j0, L, R, d2w);
            #pragma unroll
            for (int k = 0; k < 4; ++k) {
                w0[k] =  hdt * (d0v[k] + a0v[k]);
                w1[k] = -qdt * d2w[k + 2];
                w2[k] =  qdt * d2w[k];
            }
        } else {
            #pragma unroll
            for (int k = 0; k < 4; ++k) { w0[k] = 0.f; w1[k] = 0.f; w2[k] = 0.f; }
        }
    }

    const long off = (long)i * NYC + j0;
    float4 v;
    v.x = w0[0]; v.y = w0[1]; v.z = w0[2]; v.w = w0[3];
    *reinterpret_cast<float4*>(g_w + p0 * PLANE + off) = v;
    v.x = w1[0]; v.y = w1[1]; v.z = w1[2]; v.w = w1[3];
    *reinterpret_cast<float4*>(g_w + p1 * PLANE + off) = v;
    v.x = w2[0]; v.y = w2[1]; v.z = w2[2]; v.w = w2[3];
    *reinterpret_cast<float4*>(g_w + p2 * PLANE + off) = v;
}

__global__ __launch_bounds__(TPB, 4)
void fp2d_step_kernel(const float* __restrict__ f,
                      float* __restrict__ out) {
    const int tid = threadIdx.x;
    const int j0  = tid * 4;
    const bool L  = (tid > 0);
    const bool R  = (tid < TPB - 1);
    const int i0  = blockIdx.x * ICH;
    const long b0 = (long)blockIdx.y * NBATCH;

    // per-batch row base pointers (advanced by NYC each iteration)
    const float* fb[NBATCH];
    float* ob[NBATCH];
    #pragma unroll
    for (int b = 0; b < NBATCH; ++b) {
        fb[b] = f   + (b0 + b) * PLANE + (long)i0 * NYC;  // points at row i0
        ob[b] = out + (b0 + b) * PLANE + (long)i0 * NYC;
    }

    // f windows: [m] = f[row][j0+m-1], rotated along i
    float fm[NBATCH][6], fc[NBATCH][6], fp[NBATCH][6];

    // ---------------- prologue: f rows i0-1 and i0 ----------------
    if (i0 > 0) {
        #pragma unroll
        for (int b = 0; b < NBATCH; ++b)
            win6_g(fb[b] - NYC, j0, L, R, fm[b]);
    } else {
        #pragma unroll
        for (int b = 0; b < NBATCH; ++b)
            #pragma unroll
            for (int m = 0; m < 6; ++m) fm[b][m] = 0.0f;
    }
    #pragma unroll
    for (int b = 0; b < NBATCH; ++b)
        win6_g(fb[b], j0, L, R, fc[b]);

    // ---------------- main i-march ----------------
    for (int i = i0; i < i0 + ICH; ++i) {
        const int ip = i + 1;

        // 1) load f row i+1 (the only DRAM-new data this iteration)
        if (ip < NXC) {
            #pragma unroll
            for (int b = 0; b < NBATCH; ++b)
                win6_g(fb[b] + NYC, j0, L, R, fp[b]);
        } else {
            #pragma unroll
            for (int b = 0; b < NBATCH; ++b)
                #pragma unroll
                for (int m = 0; m < 6; ++m) fp[b][m] = 0.0f;
        }

        // 2) load the 9 precomputed weight vectors for row i (L2-hot)
        float4 w[9];
        const float* wrow = g_w + (long)i * NYC + j0;
        #pragma unroll
        for (int p = 0; p < 9; ++p)
            w[p] = __ldg(reinterpret_cast<const float4*>(wrow + p * PLANE));

        // 3) compute + streaming-store outputs for row i
        #pragma unroll
        for (int b = 0; b < NBATCH; ++b) {
            float rv[4];
            #pragma unroll
            for (int k = 0; k < 4; ++k) {
                const float wc  = (&w[0].x)[k];
                const float wxp = (&w[1].x)[k];
                const float wxm = (&w[2].x)[k];
                const float wyp = (&w[3].x)[k];
                const float wym = (&w[4].x)[k];
                const float wpp = (&w[5].x)[k];
                const float wpm = (&w[6].x)[k];
                const float wmp = (&w[7].x)[k];
                const float wmm = (&w[8].x)[k];
                float v = wc  * fc[b][k + 1];
                v += wxp * fp[b][k + 1];
                v += wxm * fm[b][k + 1];
                v += wyp * fc[b][k + 2];
                v += wym * fc[b][k];
                v += wpp * fp[b][k + 2];
                v += wpm * fp[b][k];
                v += wmp * fm[b][k + 2];
                v += wmm * fm[b][k];
                rv[k] = fmaxf(v, 0.0f);
            }
            float4 res;
            res.x = rv[0]; res.y = rv[1]; res.z = rv[2]; res.w = rv[3];
            __stcs(reinterpret_cast<float4*>(ob[b] + j0), res);
        }

        // 4) rotate f windows (fp -> fc -> fm), advance row pointers
        #pragma unroll
        for (int b = 0; b < NBATCH; ++b) {
            #pragma unroll
            for (int m = 0; m < 6; ++m) {
                fm[b][m] = fc[b][m];
                fc[b][m] = fp[b][m];
            }
            fb[b] += NYC;
            ob[b] += NYC;
        }
    }
}

extern "C" void kernel_launch(void* const* d_in, const int* in_sizes, int n_in,
                              void* d_out, int out_size) {
    const float* f  = (const float*)d_in[0];
    const float* A  = (const float*)d_in[1];
    const float* D  = (const float*)d_in[2];
    const float* dt = (const float*)d_in[3];
    float* out = (float*)d_out;

    const int plane = NXC * NYC;
    const int B = in_sizes[0] / plane;   // 128

    dim3 wgrid(NXC, 3);
    fp2d_weights_kernel<<<wgrid, TPB>>>(A, D, dt);
    dim3 grid(NXC / ICH, B / NBATCH);    // (32, 32)
    fp2d_step_kernel<<<grid, TPB>>>(f, out);
}